// round 1
// baseline (speedup 1.0000x reference)
#include <cuda_runtime.h>
#include <cuda_bf16.h>
#include <cstdint>

// ===================== problem constants =====================
constexpr int B_  = 8;
constexpr int LQ_ = 2048;
constexpr int LK_ = 2048;
constexpr int D_  = 128;

constexpr int BM = 128;   // q rows per CTA
constexpr int BN = 64;    // kv rows per iteration
constexpr int PITCH = 136; // smem row pitch in bf16 elems (128 + 8 pad -> conflict-free ldmatrix)
constexpr int NT = LK_ / BN; // 32 kv tiles

constexpr float SCALE = 0.08838834764831845f; // 1/sqrt(128)

constexpr int Q_ELEMS     = BM * PITCH;        // 17408
constexpr int KV_ELEMS    = BN * PITCH;        // 8704
constexpr int STAGE_ELEMS = 4 * KV_ELEMS;      // Kh,Kl,Vh,Vl = 34816
constexpr int SMEM_ELEMS  = 2 * Q_ELEMS + 2 * STAGE_ELEMS; // 104448
constexpr int SMEM_BYTES  = SMEM_ELEMS * 2;    // 208896

// ===================== device scratch (hi/lo bf16 splits) =====================
__device__ __nv_bfloat16 g_qh[B_ * LQ_ * D_];
__device__ __nv_bfloat16 g_ql[B_ * LQ_ * D_];
__device__ __nv_bfloat16 g_kh[B_ * LK_ * D_];
__device__ __nv_bfloat16 g_kl[B_ * LK_ * D_];
__device__ __nv_bfloat16 g_vh[B_ * LK_ * D_];
__device__ __nv_bfloat16 g_vl[B_ * LK_ * D_];

// ===================== small asm helpers =====================
__device__ __forceinline__ void cp_async16(uint32_t dst, const void* src) {
    asm volatile("cp.async.cg.shared.global [%0], [%1], 16;" :: "r"(dst), "l"(src));
}
__device__ __forceinline__ void cp_commit() {
    asm volatile("cp.async.commit_group;");
}
template <int N>
__device__ __forceinline__ void cp_wait() {
    asm volatile("cp.async.wait_group %0;" :: "n"(N));
}
__device__ __forceinline__ void ldsm4(uint32_t* r, uint32_t addr) {
    asm volatile("ldmatrix.sync.aligned.m8n8.x4.shared.b16 {%0,%1,%2,%3}, [%4];"
                 : "=r"(r[0]), "=r"(r[1]), "=r"(r[2]), "=r"(r[3]) : "r"(addr));
}
__device__ __forceinline__ void ldsm4t(uint32_t* r, uint32_t addr) {
    asm volatile("ldmatrix.sync.aligned.m8n8.x4.trans.shared.b16 {%0,%1,%2,%3}, [%4];"
                 : "=r"(r[0]), "=r"(r[1]), "=r"(r[2]), "=r"(r[3]) : "r"(addr));
}
__device__ __forceinline__ void mma16816(float* c, const uint32_t* a, uint32_t b0, uint32_t b1) {
    asm volatile(
        "mma.sync.aligned.m16n8k16.row.col.f32.bf16.bf16.f32 "
        "{%0,%1,%2,%3}, {%4,%5,%6,%7}, {%8,%9}, {%0,%1,%2,%3};"
        : "+f"(c[0]), "+f"(c[1]), "+f"(c[2]), "+f"(c[3])
        : "r"(a[0]), "r"(a[1]), "r"(a[2]), "r"(a[3]), "r"(b0), "r"(b1));
}
__device__ __forceinline__ float sigmoidf_fast(float x) {
    return __fdividef(1.0f, 1.0f + __expf(-x));
}
// pack two fp32 into hi-bf16x2 and lo-bf16x2 (x in low half, y in high half)
__device__ __forceinline__ void split2(float x, float y, uint32_t& h, uint32_t& l) {
    __nv_bfloat16 hx = __float2bfloat16(x);
    __nv_bfloat16 hy = __float2bfloat16(y);
    float lx = x - __bfloat162float(hx);
    float ly = y - __bfloat162float(hy);
    __nv_bfloat162 hp = __halves2bfloat162(hx, hy);
    __nv_bfloat162 lp = __floats2bfloat162_rn(lx, ly);
    h = *reinterpret_cast<uint32_t*>(&hp);
    l = *reinterpret_cast<uint32_t*>(&lp);
}

// ===================== prep: fp32 -> (hi,lo) bf16 =====================
__global__ void split_kernel(const float* __restrict__ q,
                             const float* __restrict__ k,
                             const float* __restrict__ v) {
    const int t = blockIdx.y;
    const float* s = (t == 0) ? q : (t == 1) ? k : v;
    __nv_bfloat16* H = (t == 0) ? g_qh : (t == 1) ? g_kh : g_vh;
    __nv_bfloat16* L = (t == 0) ? g_ql : (t == 1) ? g_kl : g_vl;
    const int i = (blockIdx.x * blockDim.x + threadIdx.x) * 4;
    float4 x = *reinterpret_cast<const float4*>(s + i);

    __nv_bfloat16 h0 = __float2bfloat16(x.x);
    __nv_bfloat16 h1 = __float2bfloat16(x.y);
    __nv_bfloat16 h2 = __float2bfloat16(x.z);
    __nv_bfloat16 h3 = __float2bfloat16(x.w);
    float l0 = x.x - __bfloat162float(h0);
    float l1 = x.y - __bfloat162float(h1);
    float l2 = x.z - __bfloat162float(h2);
    float l3 = x.w - __bfloat162float(h3);

    reinterpret_cast<__nv_bfloat162*>(H + i)[0] = __halves2bfloat162(h0, h1);
    reinterpret_cast<__nv_bfloat162*>(H + i)[1] = __halves2bfloat162(h2, h3);
    reinterpret_cast<__nv_bfloat162*>(L + i)[0] = __floats2bfloat162_rn(l0, l1);
    reinterpret_cast<__nv_bfloat162*>(L + i)[1] = __floats2bfloat162_rn(l2, l3);
}

// ===================== kv tile loader =====================
__device__ __forceinline__ void load_kv(uint32_t smb, int b, int kt, int stg, int tid) {
    const size_t base = ((size_t)b * LK_ + (size_t)kt * BN) * D_;
    const __nv_bfloat16* gs[4] = { g_kh + base, g_kl + base, g_vh + base, g_vl + base };
#pragma unroll
    for (int a = 0; a < 4; a++) {
#pragma unroll
        for (int tt = 0; tt < 4; tt++) {
            int idx = tt * 256 + tid;
            int row = idx >> 4, c = idx & 15;
            cp_async16(smb + (uint32_t)((2 * Q_ELEMS + stg * STAGE_ELEMS + a * KV_ELEMS +
                                         row * PITCH + c * 8) * 2),
                       gs[a] + row * D_ + c * 8);
        }
    }
}

// ===================== main attention kernel =====================
__global__ void __launch_bounds__(256, 1)
attn_kernel(const int* __restrict__ mask, float* __restrict__ out) {
    extern __shared__ __nv_bfloat16 sm[];
    const int tid  = threadIdx.x;
    const int lane = tid & 31;
    const int w    = tid >> 5;
    const int qt   = blockIdx.x;
    const int b    = blockIdx.y;
    const int qbase = qt * BM;

    const uint32_t smb = (uint32_t)__cvta_generic_to_shared(sm);

    // ---- async load Q tile (hi/lo), then KV stage 0, one commit group
    {
        const __nv_bfloat16* gq[2] = {
            g_qh + ((size_t)b * LQ_ + qbase) * D_,
            g_ql + ((size_t)b * LQ_ + qbase) * D_
        };
#pragma unroll
        for (int a = 0; a < 2; a++) {
#pragma unroll
            for (int tt = 0; tt < 8; tt++) {
                int idx = tt * 256 + tid;
                int row = idx >> 4, c = idx & 15;
                cp_async16(smb + (uint32_t)((a * Q_ELEMS + row * PITCH + c * 8) * 2),
                           gq[a] + row * D_ + c * 8);
            }
        }
    }
    load_kv(smb, b, 0, 0, tid);
    cp_commit();

    // ---- per-thread ldmatrix base offsets
    const int l8  = lane & 7;
    const int grp = lane >> 3;
    const uint32_t a_off = (uint32_t)(((w * 16 + (lane & 15)) * PITCH + (lane >> 4) * 8) * 2);
    const uint32_t aQh = smb + a_off;
    const uint32_t aQl = smb + (uint32_t)(Q_ELEMS * 2) + a_off;
    // K (B operand, non-trans): lanes 0-7:(n,k0) 8-15:(n,k8) 16-23:(n+8,k0) 24-31:(n+8,k8)
    const uint32_t b_off = (uint32_t)((((grp >> 1) * 8 + l8) * PITCH + (grp & 1) * 8) * 2);
    // V (B operand, trans): lanes 0-7:(kv,d0) 8-15:(kv+8,d0) 16-23:(kv,d8) 24-31:(kv+8,d8)
    const uint32_t v_off = (uint32_t)((((grp & 1) * 8 + l8) * PITCH + (grp >> 1) * 8) * 2);

    // ---- mask / output row mapping (accumulator fragment rows)
    const int g0 = qbase + w * 16 + (lane >> 2);
    const int q2 = (lane & 3) * 2;
    const int* mrow0 = mask + ((size_t)b * LQ_ + g0) * LK_;
    const int* mrow1 = mrow0 + (size_t)8 * LK_;

    float oacc[16][4];
#pragma unroll
    for (int i = 0; i < 16; i++)
#pragma unroll
        for (int e = 0; e < 4; e++) oacc[i][e] = 0.0f;

#pragma unroll 1
    for (int kt = 0; kt < NT; ++kt) {
        if (kt + 1 < NT) {
            load_kv(smb, b, kt + 1, (kt + 1) & 1, tid);
            cp_commit();
            cp_wait<1>();
        } else {
            cp_wait<0>();
        }
        __syncthreads();

        // prefetch mask fragments for this kv tile (hidden under the QK MMAs)
        int2 m0[8], m1[8];
#pragma unroll
        for (int j = 0; j < 8; j++) {
            int col = kt * BN + j * 8 + q2;
            m0[j] = *reinterpret_cast<const int2*>(mrow0 + col);
            m1[j] = *reinterpret_cast<const int2*>(mrow1 + col);
        }

        const uint32_t stage = smb + (uint32_t)((2 * Q_ELEMS + (kt & 1) * STAGE_ELEMS) * 2);
        const uint32_t sKh = stage;
        const uint32_t sKl = stage + (uint32_t)(KV_ELEMS * 2);
        const uint32_t sVh = stage + (uint32_t)(2 * KV_ELEMS * 2);
        const uint32_t sVl = stage + (uint32_t)(3 * KV_ELEMS * 2);

        // ======== S = Q K^T  (bf16 hi/lo, 3 passes) ========
        float sacc[8][4];
#pragma unroll
        for (int j = 0; j < 8; j++)
#pragma unroll
            for (int e = 0; e < 4; e++) sacc[j][e] = 0.0f;

#pragma unroll
        for (int k16 = 0; k16 < 8; k16++) {
            uint32_t ah[4], al[4];
            ldsm4(ah, aQh + k16 * 32);
            ldsm4(al, aQl + k16 * 32);
#pragma unroll
            for (int jp = 0; jp < 4; jp++) {
                uint32_t bh[4], bl[4];
                uint32_t off = b_off + (uint32_t)(jp * 16 * PITCH * 2) + k16 * 32;
                ldsm4(bh, sKh + off);
                ldsm4(bl, sKl + off);
                mma16816(sacc[2 * jp],     ah, bh[0], bh[1]);
                mma16816(sacc[2 * jp],     ah, bl[0], bl[1]);
                mma16816(sacc[2 * jp],     al, bh[0], bh[1]);
                mma16816(sacc[2 * jp + 1], ah, bh[2], bh[3]);
                mma16816(sacc[2 * jp + 1], ah, bl[2], bl[3]);
                mma16816(sacc[2 * jp + 1], al, bh[2], bh[3]);
            }
        }

        // ======== P = mask ? 0 : sigmoid(S/sqrt(d)) ========
#pragma unroll
        for (int j = 0; j < 8; j++) {
            sacc[j][0] = m0[j].x ? 0.0f : sigmoidf_fast(sacc[j][0] * SCALE);
            sacc[j][1] = m0[j].y ? 0.0f : sigmoidf_fast(sacc[j][1] * SCALE);
            sacc[j][2] = m1[j].x ? 0.0f : sigmoidf_fast(sacc[j][2] * SCALE);
            sacc[j][3] = m1[j].y ? 0.0f : sigmoidf_fast(sacc[j][3] * SCALE);
        }

        // ======== O += P V  (bf16 hi/lo, 3 passes; P from registers) ========
#pragma unroll
        for (int s = 0; s < 4; s++) {
            uint32_t pah[4], pal[4];
            split2(sacc[2 * s][0],     sacc[2 * s][1],     pah[0], pal[0]);
            split2(sacc[2 * s][2],     sacc[2 * s][3],     pah[1], pal[1]);
            split2(sacc[2 * s + 1][0], sacc[2 * s + 1][1], pah[2], pal[2]);
            split2(sacc[2 * s + 1][2], sacc[2 * s + 1][3], pah[3], pal[3]);
#pragma unroll
            for (int jp = 0; jp < 8; jp++) {
                uint32_t vh[4], vl[4];
                uint32_t off = v_off + (uint32_t)(s * 16 * PITCH * 2) + jp * 32;
                ldsm4t(vh, sVh + off);
                ldsm4t(vl, sVl + off);
                mma16816(oacc[2 * jp],     pah, vh[0], vh[1]);
                mma16816(oacc[2 * jp],     pah, vl[0], vl[1]);
                mma16816(oacc[2 * jp],     pal, vh[0], vh[1]);
                mma16816(oacc[2 * jp + 1], pah, vh[2], vh[3]);
                mma16816(oacc[2 * jp + 1], pah, vl[2], vl[3]);
                mma16816(oacc[2 * jp + 1], pal, vh[2], vh[3]);
            }
        }
        __syncthreads();
    }

    // ---- write O
    float* o0 = out + ((size_t)b * LQ_ + g0) * D_;
    float* o1 = o0 + (size_t)8 * D_;
#pragma unroll
    for (int jd = 0; jd < 16; jd++) {
        int col = jd * 8 + q2;
        *reinterpret_cast<float2*>(o0 + col) = make_float2(oacc[jd][0], oacc[jd][1]);
        *reinterpret_cast<float2*>(o1 + col) = make_float2(oacc[jd][2], oacc[jd][3]);
    }
}

// ===================== launch =====================
extern "C" void kernel_launch(void* const* d_in, const int* in_sizes, int n_in,
                              void* d_out, int out_size) {
    const float* q    = (const float*)d_in[0];
    const float* k    = (const float*)d_in[1];
    const float* v    = (const float*)d_in[2];
    const int*   mask = (const int*)d_in[3];
    float*       out  = (float*)d_out;

    cudaFuncSetAttribute(attn_kernel, cudaFuncAttributeMaxDynamicSharedMemorySize, SMEM_BYTES);

    // split q,k,v into bf16 hi/lo
    split_kernel<<<dim3((B_ * LQ_ * D_ / 4) / 256, 3), 256>>>(q, k, v);

    // fused sigmoid-attention
    attn_kernel<<<dim3(LQ_ / BM, B_), 256, SMEM_BYTES>>>(mask, out);
}

// round 2
// speedup vs baseline: 1.2901x; 1.2901x over previous
#include <cuda_runtime.h>
#include <cuda_fp16.h>
#include <cstdint>

// ===================== problem constants =====================
constexpr int B_  = 8;
constexpr int LQ_ = 2048;
constexpr int LK_ = 2048;
constexpr int D_  = 128;

constexpr int BM = 128;    // q rows per CTA
constexpr int BN = 64;     // kv rows per iteration
constexpr int PITCH = 136; // smem row pitch in fp16 elems (128 + 8 pad -> conflict-free ldmatrix)
constexpr int NT = LK_ / BN; // 32 kv tiles

constexpr float SCALE = 0.08838834764831845f; // 1/sqrt(128)

constexpr int Q_ELEMS     = BM * PITCH;            // 17408
constexpr int KV_ELEMS    = BN * PITCH;            // 8704
constexpr int STAGE_ELEMS = 2 * KV_ELEMS;          // K,V = 17408
constexpr int SMEM_ELEMS  = Q_ELEMS + 2 * STAGE_ELEMS; // 52224
constexpr int SMEM_BYTES  = SMEM_ELEMS * 2;        // 104448

// ===================== device scratch (fp16 casts) =====================
__device__ __half g_q[B_ * LQ_ * D_];
__device__ __half g_k[B_ * LK_ * D_];
__device__ __half g_v[B_ * LK_ * D_];

// ===================== small asm helpers =====================
__device__ __forceinline__ void cp_async16(uint32_t dst, const void* src) {
    asm volatile("cp.async.cg.shared.global [%0], [%1], 16;" :: "r"(dst), "l"(src));
}
__device__ __forceinline__ void cp_commit() {
    asm volatile("cp.async.commit_group;");
}
template <int N>
__device__ __forceinline__ void cp_wait() {
    asm volatile("cp.async.wait_group %0;" :: "n"(N));
}
__device__ __forceinline__ void ldsm4(uint32_t* r, uint32_t addr) {
    asm volatile("ldmatrix.sync.aligned.m8n8.x4.shared.b16 {%0,%1,%2,%3}, [%4];"
                 : "=r"(r[0]), "=r"(r[1]), "=r"(r[2]), "=r"(r[3]) : "r"(addr));
}
__device__ __forceinline__ void ldsm4t(uint32_t* r, uint32_t addr) {
    asm volatile("ldmatrix.sync.aligned.m8n8.x4.trans.shared.b16 {%0,%1,%2,%3}, [%4];"
                 : "=r"(r[0]), "=r"(r[1]), "=r"(r[2]), "=r"(r[3]) : "r"(addr));
}
__device__ __forceinline__ void mma16816(float* c, const uint32_t* a, uint32_t b0, uint32_t b1) {
    asm volatile(
        "mma.sync.aligned.m16n8k16.row.col.f32.f16.f16.f32 "
        "{%0,%1,%2,%3}, {%4,%5,%6,%7}, {%8,%9}, {%0,%1,%2,%3};"
        : "+f"(c[0]), "+f"(c[1]), "+f"(c[2]), "+f"(c[3])
        : "r"(a[0]), "r"(a[1]), "r"(a[2]), "r"(a[3]), "r"(b0), "r"(b1));
}
__device__ __forceinline__ float sigmoidf_fast(float x) {
    return __fdividef(1.0f, 1.0f + __expf(-x));
}
__device__ __forceinline__ uint32_t pack2h(float x, float y) {
    __half2 h = __floats2half2_rn(x, y);
    return *reinterpret_cast<uint32_t*>(&h);
}

// ===================== prep: fp32 -> fp16 =====================
__global__ void split_kernel(const float* __restrict__ q,
                             const float* __restrict__ k,
                             const float* __restrict__ v) {
    const int t = blockIdx.y;
    const float* s = (t == 0) ? q : (t == 1) ? k : v;
    __half* H = (t == 0) ? g_q : (t == 1) ? g_k : g_v;
    const int i = (blockIdx.x * blockDim.x + threadIdx.x) * 4;
    float4 x = *reinterpret_cast<const float4*>(s + i);
    reinterpret_cast<__half2*>(H + i)[0] = __floats2half2_rn(x.x, x.y);
    reinterpret_cast<__half2*>(H + i)[1] = __floats2half2_rn(x.z, x.w);
}

// ===================== kv tile loader =====================
__device__ __forceinline__ void load_kv(uint32_t smb, int b, int kt, int stg, int tid) {
    const size_t base = ((size_t)b * LK_ + (size_t)kt * BN) * D_;
    const __half* gs[2] = { g_k + base, g_v + base };
#pragma unroll
    for (int a = 0; a < 2; a++) {
#pragma unroll
        for (int tt = 0; tt < 4; tt++) {
            int idx = tt * 256 + tid;
            int row = idx >> 4, c = idx & 15;
            cp_async16(smb + (uint32_t)((Q_ELEMS + stg * STAGE_ELEMS + a * KV_ELEMS +
                                         row * PITCH + c * 8) * 2),
                       gs[a] + row * D_ + c * 8);
        }
    }
}

// ===================== main attention kernel =====================
__global__ void __launch_bounds__(256, 2)
attn_kernel(const int* __restrict__ mask, float* __restrict__ out) {
    extern __shared__ __half sm[];
    const int tid  = threadIdx.x;
    const int lane = tid & 31;
    const int w    = tid >> 5;
    const int qt   = blockIdx.x;
    const int b    = blockIdx.y;
    const int qbase = qt * BM;

    const uint32_t smb = (uint32_t)__cvta_generic_to_shared(sm);

    // ---- async load Q tile, then KV stage 0, one commit group
    {
        const __half* gq = g_q + ((size_t)b * LQ_ + qbase) * D_;
#pragma unroll
        for (int tt = 0; tt < 8; tt++) {
            int idx = tt * 256 + tid;
            int row = idx >> 4, c = idx & 15;
            cp_async16(smb + (uint32_t)((row * PITCH + c * 8) * 2),
                       gq + row * D_ + c * 8);
        }
    }
    load_kv(smb, b, 0, 0, tid);
    cp_commit();

    // ---- per-thread ldmatrix base offsets
    const int l8  = lane & 7;
    const int grp = lane >> 3;
    const uint32_t aQ = smb + (uint32_t)(((w * 16 + (lane & 15)) * PITCH + (lane >> 4) * 8) * 2);
    // K (B operand, non-trans): lanes 0-7:(n,k0) 8-15:(n,k8) 16-23:(n+8,k0) 24-31:(n+8,k8)
    const uint32_t b_off = (uint32_t)((((grp >> 1) * 8 + l8) * PITCH + (grp & 1) * 8) * 2);
    // V (B operand, trans): lanes 0-7:(kv,d0) 8-15:(kv+8,d0) 16-23:(kv,d8) 24-31:(kv+8,d8)
    const uint32_t v_off = (uint32_t)((((grp & 1) * 8 + l8) * PITCH + (grp >> 1) * 8) * 2);

    // ---- mask / output row mapping (accumulator fragment rows)
    const int g0 = qbase + w * 16 + (lane >> 2);
    const int q2 = (lane & 3) * 2;
    const int* mrow0 = mask + ((size_t)b * LQ_ + g0) * LK_;
    const int* mrow1 = mrow0 + (size_t)8 * LK_;

    float oacc[16][4];
#pragma unroll
    for (int i = 0; i < 16; i++)
#pragma unroll
        for (int e = 0; e < 4; e++) oacc[i][e] = 0.0f;

#pragma unroll 1
    for (int kt = 0; kt < NT; ++kt) {
        if (kt + 1 < NT) {
            load_kv(smb, b, kt + 1, (kt + 1) & 1, tid);
            cp_commit();
            cp_wait<1>();
        } else {
            cp_wait<0>();
        }
        __syncthreads();

        // prefetch mask fragments for this kv tile (hidden under the QK MMAs)
        int2 m0[8], m1[8];
#pragma unroll
        for (int j = 0; j < 8; j++) {
            int col = kt * BN + j * 8 + q2;
            m0[j] = *reinterpret_cast<const int2*>(mrow0 + col);
            m1[j] = *reinterpret_cast<const int2*>(mrow1 + col);
        }

        const uint32_t sK = smb + (uint32_t)((Q_ELEMS + (kt & 1) * STAGE_ELEMS) * 2);
        const uint32_t sV = sK + (uint32_t)(KV_ELEMS * 2);

        // ======== S = Q K^T (fp16 single pass, fp32 accum) ========
        float sacc[8][4];
#pragma unroll
        for (int j = 0; j < 8; j++)
#pragma unroll
            for (int e = 0; e < 4; e++) sacc[j][e] = 0.0f;

#pragma unroll
        for (int k16 = 0; k16 < 8; k16++) {
            uint32_t a[4];
            ldsm4(a, aQ + k16 * 32);
#pragma unroll
            for (int jp = 0; jp < 4; jp++) {
                uint32_t bb[4];
                ldsm4(bb, sK + b_off + (uint32_t)(jp * 16 * PITCH * 2) + k16 * 32);
                mma16816(sacc[2 * jp],     a, bb[0], bb[1]);
                mma16816(sacc[2 * jp + 1], a, bb[2], bb[3]);
            }
        }

        // ======== P = mask ? 0 : sigmoid(S/sqrt(d)) ========
#pragma unroll
        for (int j = 0; j < 8; j++) {
            sacc[j][0] = m0[j].x ? 0.0f : sigmoidf_fast(sacc[j][0] * SCALE);
            sacc[j][1] = m0[j].y ? 0.0f : sigmoidf_fast(sacc[j][1] * SCALE);
            sacc[j][2] = m1[j].x ? 0.0f : sigmoidf_fast(sacc[j][2] * SCALE);
            sacc[j][3] = m1[j].y ? 0.0f : sigmoidf_fast(sacc[j][3] * SCALE);
        }

        // ======== O += P V  (P from registers) ========
#pragma unroll
        for (int s = 0; s < 4; s++) {
            uint32_t pa[4];
            pa[0] = pack2h(sacc[2 * s][0],     sacc[2 * s][1]);
            pa[1] = pack2h(sacc[2 * s][2],     sacc[2 * s][3]);
            pa[2] = pack2h(sacc[2 * s + 1][0], sacc[2 * s + 1][1]);
            pa[3] = pack2h(sacc[2 * s + 1][2], sacc[2 * s + 1][3]);
#pragma unroll
            for (int jp = 0; jp < 8; jp++) {
                uint32_t vv[4];
                ldsm4t(vv, sV + v_off + (uint32_t)(s * 16 * PITCH * 2) + jp * 32);
                mma16816(oacc[2 * jp],     pa, vv[0], vv[1]);
                mma16816(oacc[2 * jp + 1], pa, vv[2], vv[3]);
            }
        }
        __syncthreads();
    }

    // ---- write O
    float* o0 = out + ((size_t)b * LQ_ + g0) * D_;
    float* o1 = o0 + (size_t)8 * D_;
#pragma unroll
    for (int jd = 0; jd < 16; jd++) {
        int col = jd * 8 + q2;
        *reinterpret_cast<float2*>(o0 + col) = make_float2(oacc[jd][0], oacc[jd][1]);
        *reinterpret_cast<float2*>(o1 + col) = make_float2(oacc[jd][2], oacc[jd][3]);
    }
}

// ===================== launch =====================
extern "C" void kernel_launch(void* const* d_in, const int* in_sizes, int n_in,
                              void* d_out, int out_size) {
    const float* q    = (const float*)d_in[0];
    const float* k    = (const float*)d_in[1];
    const float* v    = (const float*)d_in[2];
    const int*   mask = (const int*)d_in[3];
    float*       out  = (float*)d_out;

    cudaFuncSetAttribute(attn_kernel, cudaFuncAttributeMaxDynamicSharedMemorySize, SMEM_BYTES);

    // convert q,k,v to fp16
    split_kernel<<<dim3((B_ * LQ_ * D_ / 4) / 256, 3), 256>>>(q, k, v);

    // fused sigmoid-attention
    attn_kernel<<<dim3(LQ_ / BM, B_), 256, SMEM_BYTES>>>(mask, out);
}

// round 3
// speedup vs baseline: 2.0202x; 1.5660x over previous
#include <cuda_runtime.h>
#include <cuda_fp16.h>
#include <cstdint>

// ===================== problem constants =====================
constexpr int B_  = 8;
constexpr int LQ_ = 2048;
constexpr int LK_ = 2048;
constexpr int D_  = 128;

constexpr int BM = 64;     // q rows per CTA
constexpr int BN = 64;     // kv rows per iteration
constexpr int PITCH = 136; // smem row pitch in fp16 elems (128 + 8 pad)
constexpr int NT = LK_ / BN; // 32 kv tiles

constexpr float SCALE = 0.08838834764831845f; // 1/sqrt(128)

constexpr int Q_ELEMS     = BM * PITCH;            // 8704
constexpr int KV_ELEMS    = BN * PITCH;            // 8704
constexpr int STAGE_ELEMS = 2 * KV_ELEMS;          // K,V = 17408
constexpr int SMEM_ELEMS  = Q_ELEMS + 2 * STAGE_ELEMS; // 43520
constexpr int SMEM_BYTES  = SMEM_ELEMS * 2;        // 87040

// ===================== device scratch (fp16 casts) =====================
__device__ __half g_q[B_ * LQ_ * D_];
__device__ __half g_k[B_ * LK_ * D_];
__device__ __half g_v[B_ * LK_ * D_];

// ===================== small asm helpers =====================
__device__ __forceinline__ void cp_async16(uint32_t dst, const void* src) {
    asm volatile("cp.async.cg.shared.global [%0], [%1], 16;" :: "r"(dst), "l"(src));
}
__device__ __forceinline__ void cp_commit() {
    asm volatile("cp.async.commit_group;");
}
template <int N>
__device__ __forceinline__ void cp_wait() {
    asm volatile("cp.async.wait_group %0;" :: "n"(N));
}
__device__ __forceinline__ void ldsm4(uint32_t* r, uint32_t addr) {
    asm volatile("ldmatrix.sync.aligned.m8n8.x4.shared.b16 {%0,%1,%2,%3}, [%4];"
                 : "=r"(r[0]), "=r"(r[1]), "=r"(r[2]), "=r"(r[3]) : "r"(addr));
}
__device__ __forceinline__ void ldsm4t(uint32_t* r, uint32_t addr) {
    asm volatile("ldmatrix.sync.aligned.m8n8.x4.trans.shared.b16 {%0,%1,%2,%3}, [%4];"
                 : "=r"(r[0]), "=r"(r[1]), "=r"(r[2]), "=r"(r[3]) : "r"(addr));
}
__device__ __forceinline__ void mma16816(float* c, const uint32_t* a, uint32_t b0, uint32_t b1) {
    asm volatile(
        "mma.sync.aligned.m16n8k16.row.col.f32.f16.f16.f32 "
        "{%0,%1,%2,%3}, {%4,%5,%6,%7}, {%8,%9}, {%0,%1,%2,%3};"
        : "+f"(c[0]), "+f"(c[1]), "+f"(c[2]), "+f"(c[3])
        : "r"(a[0]), "r"(a[1]), "r"(a[2]), "r"(a[3]), "r"(b0), "r"(b1));
}
__device__ __forceinline__ float sigmoidf_fast(float x) {
    return __fdividef(1.0f, 1.0f + __expf(-x));
}
__device__ __forceinline__ uint32_t pack2h(float x, float y) {
    __half2 h = __floats2half2_rn(x, y);
    return *reinterpret_cast<uint32_t*>(&h);
}

// ===================== prep: fp32 -> fp16 =====================
__global__ void split_kernel(const float* __restrict__ q,
                             const float* __restrict__ k,
                             const float* __restrict__ v) {
    const int t = blockIdx.y;
    const float* s = (t == 0) ? q : (t == 1) ? k : v;
    __half* H = (t == 0) ? g_q : (t == 1) ? g_k : g_v;
    const int i = (blockIdx.x * blockDim.x + threadIdx.x) * 4;
    float4 x = *reinterpret_cast<const float4*>(s + i);
    reinterpret_cast<__half2*>(H + i)[0] = __floats2half2_rn(x.x, x.y);
    reinterpret_cast<__half2*>(H + i)[1] = __floats2half2_rn(x.z, x.w);
}

// ===================== kv tile loader (K+V, 64 rows each) =====================
__device__ __forceinline__ void load_kv(uint32_t smb, int b, int kt, int stg, int tid) {
    const size_t base = ((size_t)b * LK_ + (size_t)kt * BN) * D_;
    const __half* gs[2] = { g_k + base, g_v + base };
#pragma unroll
    for (int a = 0; a < 2; a++) {
#pragma unroll
        for (int tt = 0; tt < 4; tt++) {
            int idx = tt * 256 + tid;
            int row = idx >> 4, c = idx & 15;
            cp_async16(smb + (uint32_t)((Q_ELEMS + stg * STAGE_ELEMS + a * KV_ELEMS +
                                         row * PITCH + c * 8) * 2),
                       gs[a] + row * D_ + c * 8);
        }
    }
}

// ===================== main attention kernel =====================
// 8 warps: mg = w&3 picks 16 q-rows (BM=64), ng = w>>2 picks 32 of the 64 kv cols.
// Each warp accumulates a partial 16x128 O over its kv-column half; halves are
// summed once at the end through smem.
__global__ void __launch_bounds__(256, 2)
attn_kernel(const int* __restrict__ mask, float* __restrict__ out) {
    extern __shared__ __half sm[];
    const int tid  = threadIdx.x;
    const int lane = tid & 31;
    const int w    = tid >> 5;
    const int mg   = w & 3;
    const int ng   = w >> 2;
    const int qt   = blockIdx.x;
    const int b    = blockIdx.y;
    const int qbase = qt * BM;

    const uint32_t smb = (uint32_t)__cvta_generic_to_shared(sm);

    // ---- async load Q tile, then KV stage 0, one commit group
    {
        const __half* gq = g_q + ((size_t)b * LQ_ + qbase) * D_;
#pragma unroll
        for (int tt = 0; tt < 4; tt++) {
            int idx = tt * 256 + tid;
            int row = idx >> 4, c = idx & 15;
            cp_async16(smb + (uint32_t)((row * PITCH + c * 8) * 2),
                       gq + row * D_ + c * 8);
        }
    }
    load_kv(smb, b, 0, 0, tid);
    cp_commit();

    // ---- per-thread ldmatrix base offsets
    const int l8  = lane & 7;
    const int grp = lane >> 3;
    const uint32_t aQ = smb + (uint32_t)(((mg * 16 + (lane & 15)) * PITCH + (lane >> 4) * 8) * 2);
    // K (B operand, non-trans)
    const uint32_t b_off = (uint32_t)((((grp >> 1) * 8 + l8) * PITCH + (grp & 1) * 8) * 2);
    // V (B operand, trans)
    const uint32_t v_off = (uint32_t)((((grp & 1) * 8 + l8) * PITCH + (grp >> 1) * 8) * 2);

    const int ncol0 = ng * 32;          // this warp's kv-column base within the tile

    // ---- mask / output row mapping (accumulator fragment rows)
    const int g0 = qbase + mg * 16 + (lane >> 2);
    const int q2 = (lane & 3) * 2;
    const int* mrow0 = mask + ((size_t)b * LQ_ + g0) * LK_;
    const int* mrow1 = mrow0 + (size_t)8 * LK_;

    float oacc[16][4];
#pragma unroll
    for (int i = 0; i < 16; i++)
#pragma unroll
        for (int e = 0; e < 4; e++) oacc[i][e] = 0.0f;

#pragma unroll 1
    for (int kt = 0; kt < NT; ++kt) {
        if (kt + 1 < NT) {
            load_kv(smb, b, kt + 1, (kt + 1) & 1, tid);
            cp_commit();
            cp_wait<1>();
        } else {
            cp_wait<0>();
        }
        __syncthreads();

        // prefetch mask fragments for this warp's 32 kv cols
        int2 m0[4], m1[4];
#pragma unroll
        for (int j = 0; j < 4; j++) {
            int col = kt * BN + ncol0 + j * 8 + q2;
            m0[j] = *reinterpret_cast<const int2*>(mrow0 + col);
            m1[j] = *reinterpret_cast<const int2*>(mrow1 + col);
        }

        const uint32_t sK = smb + (uint32_t)((Q_ELEMS + (kt & 1) * STAGE_ELEMS) * 2);
        const uint32_t sV = sK + (uint32_t)(KV_ELEMS * 2);

        // ======== S = Q K^T over this warp's 16x32 block ========
        float sacc[4][4];
#pragma unroll
        for (int j = 0; j < 4; j++)
#pragma unroll
            for (int e = 0; e < 4; e++) sacc[j][e] = 0.0f;

#pragma unroll
        for (int k16 = 0; k16 < 8; k16++) {
            uint32_t a[4];
            ldsm4(a, aQ + k16 * 32);
#pragma unroll
            for (int jp = 0; jp < 2; jp++) {
                uint32_t bb[4];
                ldsm4(bb, sK + b_off + (uint32_t)(((ncol0 + jp * 16) * PITCH) * 2) + k16 * 32);
                mma16816(sacc[2 * jp],     a, bb[0], bb[1]);
                mma16816(sacc[2 * jp + 1], a, bb[2], bb[3]);
            }
        }

        // ======== P = mask ? 0 : sigmoid(S/sqrt(d)) ========
#pragma unroll
        for (int j = 0; j < 4; j++) {
            sacc[j][0] = m0[j].x ? 0.0f : sigmoidf_fast(sacc[j][0] * SCALE);
            sacc[j][1] = m0[j].y ? 0.0f : sigmoidf_fast(sacc[j][1] * SCALE);
            sacc[j][2] = m1[j].x ? 0.0f : sigmoidf_fast(sacc[j][2] * SCALE);
            sacc[j][3] = m1[j].y ? 0.0f : sigmoidf_fast(sacc[j][3] * SCALE);
        }

        // ======== O += P V over this warp's 32 kv rows ========
#pragma unroll
        for (int s = 0; s < 2; s++) {
            uint32_t pa[4];
            pa[0] = pack2h(sacc[2 * s][0],     sacc[2 * s][1]);
            pa[1] = pack2h(sacc[2 * s][2],     sacc[2 * s][3]);
            pa[2] = pack2h(sacc[2 * s + 1][0], sacc[2 * s + 1][1]);
            pa[3] = pack2h(sacc[2 * s + 1][2], sacc[2 * s + 1][3]);
#pragma unroll
            for (int jp = 0; jp < 8; jp++) {
                uint32_t vv[4];
                ldsm4t(vv, sV + v_off + (uint32_t)(((ncol0 + s * 16) * PITCH) * 2) + jp * 32);
                mma16816(oacc[2 * jp],     pa, vv[0], vv[1]);
                mma16816(oacc[2 * jp + 1], pa, vv[2], vv[3]);
            }
        }
        __syncthreads();
    }

    // ---- reduce the two kv-column halves through smem, then write O
    float* smf = reinterpret_cast<float*>(sm);
    const int r0 = lane >> 2;
    if (ng == 1) {
#pragma unroll
        for (int jd = 0; jd < 16; jd++) {
            int col = jd * 8 + q2;
            float* p0 = smf + (mg * 16 + r0) * 128 + col;
            float* p1 = smf + (mg * 16 + r0 + 8) * 128 + col;
            p0[0] = oacc[jd][0]; p0[1] = oacc[jd][1];
            p1[0] = oacc[jd][2]; p1[1] = oacc[jd][3];
        }
    }
    __syncthreads();
    if (ng == 0) {
        float* o0 = out + ((size_t)b * LQ_ + g0) * D_;
        float* o1 = o0 + (size_t)8 * D_;
#pragma unroll
        for (int jd = 0; jd < 16; jd++) {
            int col = jd * 8 + q2;
            const float* p0 = smf + (mg * 16 + r0) * 128 + col;
            const float* p1 = smf + (mg * 16 + r0 + 8) * 128 + col;
            *reinterpret_cast<float2*>(o0 + col) =
                make_float2(oacc[jd][0] + p0[0], oacc[jd][1] + p0[1]);
            *reinterpret_cast<float2*>(o1 + col) =
                make_float2(oacc[jd][2] + p1[0], oacc[jd][3] + p1[1]);
        }
    }
}

// ===================== launch =====================
extern "C" void kernel_launch(void* const* d_in, const int* in_sizes, int n_in,
                              void* d_out, int out_size) {
    const float* q    = (const float*)d_in[0];
    const float* k    = (const float*)d_in[1];
    const float* v    = (const float*)d_in[2];
    const int*   mask = (const int*)d_in[3];
    float*       out  = (float*)d_out;

    cudaFuncSetAttribute(attn_kernel, cudaFuncAttributeMaxDynamicSharedMemorySize, SMEM_BYTES);

    // convert q,k,v to fp16
    split_kernel<<<dim3((B_ * LQ_ * D_ / 4) / 256, 3), 256>>>(q, k, v);

    // fused sigmoid-attention: 256 CTAs -> 2 CTAs/SM, 16 warps/SM
    attn_kernel<<<dim3(LQ_ / BM, B_), 256, SMEM_BYTES>>>(mask, out);
}

// round 5
// speedup vs baseline: 2.1303x; 1.0545x over previous
#include <cuda_runtime.h>
#include <cuda_fp16.h>
#include <cstdint>

// ===================== problem constants =====================
constexpr int B_  = 8;
constexpr int LQ_ = 2048;
constexpr int LK_ = 2048;
constexpr int D_  = 128;

constexpr int BM = 64;     // q rows per CTA
constexpr int BN = 64;     // kv rows per iteration
constexpr int PITCH = 136; // smem row pitch in fp16 elems (128 + 8 pad)
constexpr int NT = LK_ / BN; // 32 kv tiles

constexpr float SCALE = 0.08838834764831845f; // 1/sqrt(128)
constexpr float HALF_SCALE = 0.5f * SCALE;    // for sigmoid-via-tanh

constexpr int Q_ELEMS     = BM * PITCH;            // 8704
constexpr int KV_ELEMS    = BN * PITCH;            // 8704
constexpr int STAGE_ELEMS = 2 * KV_ELEMS;          // K,V = 17408
constexpr int SMEM_ELEMS  = Q_ELEMS + 2 * STAGE_ELEMS; // 43520
constexpr int SMEM_BYTES  = SMEM_ELEMS * 2;        // 87040

// ===================== device scratch (fp16 casts) =====================
__device__ __half g_q[B_ * LQ_ * D_];
__device__ __half g_k[B_ * LK_ * D_];
__device__ __half g_v[B_ * LK_ * D_];

// ===================== small asm helpers =====================
__device__ __forceinline__ void cp_async16(uint32_t dst, const void* src) {
    asm volatile("cp.async.cg.shared.global [%0], [%1], 16;" :: "r"(dst), "l"(src));
}
__device__ __forceinline__ void cp_commit() {
    asm volatile("cp.async.commit_group;");
}
template <int N>
__device__ __forceinline__ void cp_wait() {
    asm volatile("cp.async.wait_group %0;" :: "n"(N));
}
__device__ __forceinline__ void ldsm4(uint32_t* r, uint32_t addr) {
    asm volatile("ldmatrix.sync.aligned.m8n8.x4.shared.b16 {%0,%1,%2,%3}, [%4];"
                 : "=r"(r[0]), "=r"(r[1]), "=r"(r[2]), "=r"(r[3]) : "r"(addr));
}
__device__ __forceinline__ void ldsm4t(uint32_t* r, uint32_t addr) {
    asm volatile("ldmatrix.sync.aligned.m8n8.x4.trans.shared.b16 {%0,%1,%2,%3}, [%4];"
                 : "=r"(r[0]), "=r"(r[1]), "=r"(r[2]), "=r"(r[3]) : "r"(addr));
}
__device__ __forceinline__ void mma16816(float* c, const uint32_t* a, uint32_t b0, uint32_t b1) {
    asm volatile(
        "mma.sync.aligned.m16n8k16.row.col.f32.f16.f16.f32 "
        "{%0,%1,%2,%3}, {%4,%5,%6,%7}, {%8,%9}, {%0,%1,%2,%3};"
        : "+f"(c[0]), "+f"(c[1]), "+f"(c[2]), "+f"(c[3])
        : "r"(a[0]), "r"(a[1]), "r"(a[2]), "r"(a[3]), "r"(b0), "r"(b1));
}
// sigmoid(s*SCALE) = 0.5*tanh(s*SCALE/2) + 0.5  -- single MUFU op
__device__ __forceinline__ float sigmoid_fast(float s) {
    float t;
    asm("tanh.approx.f32 %0, %1;" : "=f"(t) : "f"(s * HALF_SCALE));
    return fmaf(t, 0.5f, 0.5f);
}
__device__ __forceinline__ uint32_t pack2h(float x, float y) {
    __half2 h = __floats2half2_rn(x, y);
    return *reinterpret_cast<uint32_t*>(&h);
}

// ===================== prep: fp32 -> fp16 =====================
__global__ void split_kernel(const float* __restrict__ q,
                             const float* __restrict__ k,
                             const float* __restrict__ v) {
    const int t = blockIdx.y;
    const float* s = (t == 0) ? q : (t == 1) ? k : v;
    __half* H = (t == 0) ? g_q : (t == 1) ? g_k : g_v;
    const int i = (blockIdx.x * blockDim.x + threadIdx.x) * 4;
    float4 x = *reinterpret_cast<const float4*>(s + i);
    reinterpret_cast<__half2*>(H + i)[0] = __floats2half2_rn(x.x, x.y);
    reinterpret_cast<__half2*>(H + i)[1] = __floats2half2_rn(x.z, x.w);
}

// ===================== kv tile loader (K+V, 64 rows each) =====================
__device__ __forceinline__ void load_kv(uint32_t smb, int b, int kt, int stg, int tid) {
    const size_t base = ((size_t)b * LK_ + (size_t)kt * BN) * D_;
    const __half* gs[2] = { g_k + base, g_v + base };
#pragma unroll
    for (int a = 0; a < 2; a++) {
#pragma unroll
        for (int tt = 0; tt < 4; tt++) {
            int idx = tt * 256 + tid;
            int row = idx >> 4, c = idx & 15;
            cp_async16(smb + (uint32_t)((Q_ELEMS + stg * STAGE_ELEMS + a * KV_ELEMS +
                                         row * PITCH + c * 8) * 2),
                       gs[a] + row * D_ + c * 8);
        }
    }
}

// ===================== main attention kernel =====================
// 8 warps: mg = w&3 picks 16 q-rows (BM=64), ng = w>>2 picks 32 of the 64 kv cols.
__global__ void __launch_bounds__(256, 2)
attn_kernel(const int* __restrict__ mask, float* __restrict__ out) {
    extern __shared__ __half sm[];
    const int tid  = threadIdx.x;
    const int lane = tid & 31;
    const int w    = tid >> 5;
    const int mg   = w & 3;
    const int ng   = w >> 2;
    const int qt   = blockIdx.x;
    const int b    = blockIdx.y;
    const int qbase = qt * BM;

    const uint32_t smb = (uint32_t)__cvta_generic_to_shared(sm);

    // ---- async load Q tile, then KV stage 0, one commit group
    {
        const __half* gq = g_q + ((size_t)b * LQ_ + qbase) * D_;
#pragma unroll
        for (int tt = 0; tt < 4; tt++) {
            int idx = tt * 256 + tid;
            int row = idx >> 4, c = idx & 15;
            cp_async16(smb + (uint32_t)((row * PITCH + c * 8) * 2),
                       gq + row * D_ + c * 8);
        }
    }
    load_kv(smb, b, 0, 0, tid);
    cp_commit();

    // ---- per-thread ldmatrix base offsets
    const int l8  = lane & 7;
    const int grp = lane >> 3;
    const uint32_t aQ = smb + (uint32_t)(((mg * 16 + (lane & 15)) * PITCH + (lane >> 4) * 8) * 2);
    const uint32_t b_off = (uint32_t)((((grp >> 1) * 8 + l8) * PITCH + (grp & 1) * 8) * 2);
    const uint32_t v_off = (uint32_t)((((grp & 1) * 8 + l8) * PITCH + (grp >> 1) * 8) * 2);

    const int ncol0 = ng * 32;

    // ---- mask / output row mapping (accumulator fragment rows)
    const int g0 = qbase + mg * 16 + (lane >> 2);
    const int q2 = (lane & 3) * 2;
    const int* mrow0 = mask + ((size_t)b * LQ_ + g0) * LK_;
    const int* mrow1 = mrow0 + (size_t)8 * LK_;

    float oacc[16][4];
#pragma unroll
    for (int i = 0; i < 16; i++)
#pragma unroll
        for (int e = 0; e < 4; e++) oacc[i][e] = 0.0f;

#pragma unroll 1
    for (int kt = 0; kt < NT; ++kt) {
        // mask LDGs first: fully independent of smem state, latency hides under
        // the cp.async wait, the barrier, and the S MMAs.
        int2 m0[4], m1[4];
#pragma unroll
        for (int j = 0; j < 4; j++) {
            int col = kt * BN + ncol0 + j * 8 + q2;
            m0[j] = *reinterpret_cast<const int2*>(mrow0 + col);
            m1[j] = *reinterpret_cast<const int2*>(mrow1 + col);
        }

        if (kt + 1 < NT) {
            load_kv(smb, b, kt + 1, (kt + 1) & 1, tid);
            cp_commit();
            cp_wait<1>();
        } else {
            cp_wait<0>();
        }
        __syncthreads();

        const uint32_t sK = smb + (uint32_t)((Q_ELEMS + (kt & 1) * STAGE_ELEMS) * 2);
        const uint32_t sV = sK + (uint32_t)(KV_ELEMS * 2);

        // ======== S = Q K^T over this warp's 16x32 block ========
        float sacc[4][4];
#pragma unroll
        for (int j = 0; j < 4; j++)
#pragma unroll
            for (int e = 0; e < 4; e++) sacc[j][e] = 0.0f;

#pragma unroll
        for (int k16 = 0; k16 < 8; k16++) {
            uint32_t a[4];
            ldsm4(a, aQ + k16 * 32);
#pragma unroll
            for (int jp = 0; jp < 2; jp++) {
                uint32_t bb[4];
                ldsm4(bb, sK + b_off + (uint32_t)(((ncol0 + jp * 16) * PITCH) * 2) + k16 * 32);
                mma16816(sacc[2 * jp],     a, bb[0], bb[1]);
                mma16816(sacc[2 * jp + 1], a, bb[2], bb[3]);
            }
        }

        // ======== P = mask ? 0 : sigmoid(S*scale)  (tanh.approx, 1 MUFU) ========
#pragma unroll
        for (int j = 0; j < 4; j++) {
            sacc[j][0] = m0[j].x ? 0.0f : sigmoid_fast(sacc[j][0]);
            sacc[j][1] = m0[j].y ? 0.0f : sigmoid_fast(sacc[j][1]);
            sacc[j][2] = m1[j].x ? 0.0f : sigmoid_fast(sacc[j][2]);
            sacc[j][3] = m1[j].y ? 0.0f : sigmoid_fast(sacc[j][3]);
        }

        // ======== O += P V over this warp's 32 kv rows ========
#pragma unroll
        for (int s = 0; s < 2; s++) {
            uint32_t pa[4];
            pa[0] = pack2h(sacc[2 * s][0],     sacc[2 * s][1]);
            pa[1] = pack2h(sacc[2 * s][2],     sacc[2 * s][3]);
            pa[2] = pack2h(sacc[2 * s + 1][0], sacc[2 * s + 1][1]);
            pa[3] = pack2h(sacc[2 * s + 1][2], sacc[2 * s + 1][3]);
#pragma unroll
            for (int jp = 0; jp < 8; jp++) {
                uint32_t vv[4];
                ldsm4t(vv, sV + v_off + (uint32_t)(((ncol0 + s * 16) * PITCH) * 2) + jp * 32);
                mma16816(oacc[2 * jp],     pa, vv[0], vv[1]);
                mma16816(oacc[2 * jp + 1], pa, vv[2], vv[3]);
            }
        }
        __syncthreads();
    }

    // ---- reduce the two kv-column halves through smem, then write O
    float* smf = reinterpret_cast<float*>(sm);
    const int r0 = lane >> 2;
    if (ng == 1) {
#pragma unroll
        for (int jd = 0; jd < 16; jd++) {
            int col = jd * 8 + q2;
            float* p0 = smf + (mg * 16 + r0) * 128 + col;
            float* p1 = smf + (mg * 16 + r0 + 8) * 128 + col;
            p0[0] = oacc[jd][0]; p0[1] = oacc[jd][1];
            p1[0] = oacc[jd][2]; p1[1] = oacc[jd][3];
        }
    }
    __syncthreads();
    if (ng == 0) {
        float* o0 = out + ((size_t)b * LQ_ + g0) * D_;
        float* o1 = o0 + (size_t)8 * D_;
#pragma unroll
        for (int jd = 0; jd < 16; jd++) {
            int col = jd * 8 + q2;
            const float* p0 = smf + (mg * 16 + r0) * 128 + col;
            const float* p1 = smf + (mg * 16 + r0 + 8) * 128 + col;
            *reinterpret_cast<float2*>(o0 + col) =
                make_float2(oacc[jd][0] + p0[0], oacc[jd][1] + p0[1]);
            *reinterpret_cast<float2*>(o1 + col) =
                make_float2(oacc[jd][2] + p1[0], oacc[jd][3] + p1[1]);
        }
    }
}

// ===================== launch =====================
extern "C" void kernel_launch(void* const* d_in, const int* in_sizes, int n_in,
                              void* d_out, int out_size) {
    const float* q    = (const float*)d_in[0];
    const float* k    = (const float*)d_in[1];
    const float* v    = (const float*)d_in[2];
    const int*   mask = (const int*)d_in[3];
    float*       out  = (float*)d_out;

    cudaFuncSetAttribute(attn_kernel, cudaFuncAttributeMaxDynamicSharedMemorySize, SMEM_BYTES);

    // convert q,k,v to fp16
    split_kernel<<<dim3((B_ * LQ_ * D_ / 4) / 256, 3), 256>>>(q, k, v);

    // fused sigmoid-attention: 256 CTAs -> 2 CTAs/SM, 16 warps/SM
    attn_kernel<<<dim3(LQ_ / BM, B_), 256, SMEM_BYTES>>>(mask, out);
}